// round 1
// baseline (speedup 1.0000x reference)
#include <cuda_runtime.h>

// SSIM loss: B=64, C=1, H=W=512, 11x11 uniform box window (1/121), zero (SAME) padding.
// out = 1 - mean( ret * cs ) over all pixels.
//
// Strategy: separable box filter, 4 sums per pixel:
//   E1 = box(x), E2 = box(y), E3 = box(x*y), E4 = box(x^2 + y^2)
// Each thread privately owns a 4-column group of a 64-row strip:
//   - horizontal 11-tap sliding sums from a register-resident 14-float span
//   - vertical 11-row running sums via a per-thread float4 ring buffer in shared
// No __syncthreads in the main loop; ring accesses are conflict-free LDS.128.

#define WID    512
#define HEI    512
#define BATCH  64
#define RH     64                 // output rows per strip
#define TPB    128                // 128 threads * 4 cols = 512 (full width)
#define NSTRIP (HEI / RH)         // 8
#define NBLK   (BATCH * NSTRIP)   // 512
#define RING_BYTES (11 * 4 * TPB * (int)sizeof(float4))  // 90112 B

__device__ double g_sum;

__global__ void ssim_zero_k() { g_sum = 0.0; }

__global__ void ssim_final_k(float* __restrict__ out) {
    // total pixels = 64 * 512 * 512 = 16777216
    out[0] = (float)(1.0 - g_sum * (1.0 / 16777216.0));
}

__device__ __forceinline__ float ssim_val(float e1, float e2, float e3, float e4,
                                          float w, float w2) {
    const float C1 = 1.6384f;    // (0.01*128)^2
    const float C2 = 14.7456f;   // (0.03*128)^2
    float P  = e1 * e2;
    float Q  = fmaf(e1, e1, e2 * e2);
    float A  = w2 * P;                       // mu1*mu2
    float B  = w2 * Q;                       // mu1^2 + mu2^2
    float n1 = fmaf(2.f, A, C1);             // 2*mu1mu2 + C1
    float d1 = B + C1;                       // mu1^2+mu2^2 + C1
    float n2 = fmaf(2.f * w, e3, fmaf(-2.f, A, C2));   // 2*sigma12 + C2
    float d2 = fmaf(w, e4, C2 - B);                    // sigma1+sigma2 + C2
    return __fdividef(n1 * n2, d1 * d2);
}

__global__ void __launch_bounds__(TPB, 2)
ssim_main_k(const float* __restrict__ img1, const float* __restrict__ img2,
            const float* __restrict__ window)
{
    extern __shared__ float4 ring[];   // [11 slots][4 quantities][TPB threads]
    const int h     = threadIdx.x;
    const int b     = blockIdx.x >> 3;        // image
    const int strip = blockIdx.x & (NSTRIP - 1);
    const int r0    = strip * RH;
    const int c0    = h << 2;                 // first output column of this thread

    const float w  = __ldg(window);           // 1/121
    const float w2 = w * w;

    // Span covers float columns [c0-8, c0+12): 5 aligned float4 loads.
    const float* p1 = img1 + (size_t)b * (HEI * WID) + (c0 - 8);
    const float* p2 = img2 + (size_t)b * (HEI * WID) + (c0 - 8);

    const float4 z4 = make_float4(0.f, 0.f, 0.f, 0.f);
    #pragma unroll
    for (int s = 0; s < 11; s++) {
        #pragma unroll
        for (int q = 0; q < 4; q++)
            ring[(s * 4 + q) * TPB + h] = z4;
    }

    float4 vs0 = z4, vs1 = z4, vs2 = z4, vs3 = z4;  // vertical running sums
    float acc = 0.f;
    int slot = 0;
    const bool edge = (h < 2) || (h > 125);   // span may cross the image border

    for (int r = r0 - 5; r < r0 + RH + 5; ++r) {
        float xa[20], ya[20];
        if ((unsigned)r < (unsigned)HEI) {
            const float* row1 = p1 + r * WID;
            const float* row2 = p2 + r * WID;
            if (!edge) {
                #pragma unroll
                for (int k = 0; k < 5; k++) {
                    float4 t1 = __ldg((const float4*)row1 + k);
                    float4 t2 = __ldg((const float4*)row2 + k);
                    xa[4*k+0] = t1.x; xa[4*k+1] = t1.y; xa[4*k+2] = t1.z; xa[4*k+3] = t1.w;
                    ya[4*k+0] = t2.x; ya[4*k+1] = t2.y; ya[4*k+2] = t2.z; ya[4*k+3] = t2.w;
                }
            } else {
                #pragma unroll
                for (int k = 0; k < 20; k++) {
                    int c = c0 - 8 + k;
                    bool ok = (c >= 0) && (c < WID);
                    xa[k] = ok ? __ldg(row1 + k) : 0.f;
                    ya[k] = ok ? __ldg(row2 + k) : 0.f;
                }
            }
        } else {
            #pragma unroll
            for (int k = 0; k < 20; k++) { xa[k] = 0.f; ya[k] = 0.f; }
        }

        // Horizontal 11-tap sliding sums for 4 output columns.
        // Element k corresponds to column c0-8+k; window for col c0+j is k in [3+j, 13+j].
        float4 h1, h2, h3, h4;
        {
            float s = xa[3] + xa[4] + xa[5] + xa[6] + xa[7] + xa[8] + xa[9]
                    + xa[10] + xa[11] + xa[12] + xa[13];
            h1.x = s; s += xa[14] - xa[3]; h1.y = s;
            s += xa[15] - xa[4]; h1.z = s; s += xa[16] - xa[5]; h1.w = s;
        }
        {
            float s = ya[3] + ya[4] + ya[5] + ya[6] + ya[7] + ya[8] + ya[9]
                    + ya[10] + ya[11] + ya[12] + ya[13];
            h2.x = s; s += ya[14] - ya[3]; h2.y = s;
            s += ya[15] - ya[4]; h2.z = s; s += ya[16] - ya[5]; h2.w = s;
        }
        {
            float s = xa[3] * ya[3];
            #pragma unroll
            for (int k = 4; k <= 13; k++) s = fmaf(xa[k], ya[k], s);
            h3.x = s;
            s = fmaf(xa[14], ya[14], s); s = fmaf(-xa[3], ya[3], s); h3.y = s;
            s = fmaf(xa[15], ya[15], s); s = fmaf(-xa[4], ya[4], s); h3.z = s;
            s = fmaf(xa[16], ya[16], s); s = fmaf(-xa[5], ya[5], s); h3.w = s;
        }
        {
            float s = fmaf(ya[3], ya[3], xa[3] * xa[3]);
            #pragma unroll
            for (int k = 4; k <= 13; k++) {
                s = fmaf(xa[k], xa[k], s);
                s = fmaf(ya[k], ya[k], s);
            }
            h4.x = s;
            s = fmaf(xa[14], xa[14], s); s = fmaf(ya[14], ya[14], s);
            s = fmaf(-xa[3], xa[3], s);  s = fmaf(-ya[3], ya[3], s);  h4.y = s;
            s = fmaf(xa[15], xa[15], s); s = fmaf(ya[15], ya[15], s);
            s = fmaf(-xa[4], xa[4], s);  s = fmaf(-ya[4], ya[4], s);  h4.z = s;
            s = fmaf(xa[16], xa[16], s); s = fmaf(ya[16], ya[16], s);
            s = fmaf(-xa[5], xa[5], s);  s = fmaf(-ya[5], ya[5], s);  h4.w = s;
        }

        // Vertical running sums via ring buffer (thread-private slices).
        float4 o0 = ring[(slot * 4 + 0) * TPB + h];
        float4 o1 = ring[(slot * 4 + 1) * TPB + h];
        float4 o2 = ring[(slot * 4 + 2) * TPB + h];
        float4 o3 = ring[(slot * 4 + 3) * TPB + h];
        ring[(slot * 4 + 0) * TPB + h] = h1;
        ring[(slot * 4 + 1) * TPB + h] = h2;
        ring[(slot * 4 + 2) * TPB + h] = h3;
        ring[(slot * 4 + 3) * TPB + h] = h4;
        vs0.x += h1.x - o0.x; vs0.y += h1.y - o0.y; vs0.z += h1.z - o0.z; vs0.w += h1.w - o0.w;
        vs1.x += h2.x - o1.x; vs1.y += h2.y - o1.y; vs1.z += h2.z - o1.z; vs1.w += h2.w - o1.w;
        vs2.x += h3.x - o2.x; vs2.y += h3.y - o2.y; vs2.z += h3.z - o2.z; vs2.w += h3.w - o2.w;
        vs3.x += h4.x - o3.x; vs3.y += h4.y - o3.y; vs3.z += h4.z - o3.z; vs3.w += h4.w - o3.w;
        slot = (slot == 10) ? 0 : slot + 1;

        // Emit output row r-5 once the vertical window [r-10, r] is complete.
        if (r >= r0 + 5) {
            float v0 = ssim_val(vs0.x, vs1.x, vs2.x, vs3.x, w, w2);
            float v1 = ssim_val(vs0.y, vs1.y, vs2.y, vs3.y, w, w2);
            float v2 = ssim_val(vs0.z, vs1.z, vs2.z, vs3.z, w, w2);
            float v3 = ssim_val(vs0.w, vs1.w, vs2.w, vs3.w, w, w2);
            acc += (v0 + v1) + (v2 + v3);
        }
    }

    // Block reduction -> one double atomic per block.
    #pragma unroll
    for (int o = 16; o > 0; o >>= 1)
        acc += __shfl_xor_sync(0xffffffffu, acc, o);
    __shared__ float wsum[TPB / 32];
    int wid = h >> 5, lane = h & 31;
    if (lane == 0) wsum[wid] = acc;
    __syncthreads();
    if (h == 0) {
        float s = (wsum[0] + wsum[1]) + (wsum[2] + wsum[3]);
        atomicAdd(&g_sum, (double)s);
    }
}

extern "C" void kernel_launch(void* const* d_in, const int* in_sizes, int n_in,
                              void* d_out, int out_size)
{
    const float* img1   = (const float*)d_in[0];
    const float* img2   = (const float*)d_in[1];
    const float* window = (const float*)d_in[2];
    (void)in_sizes; (void)n_in; (void)out_size;

    cudaFuncSetAttribute(ssim_main_k,
                         cudaFuncAttributeMaxDynamicSharedMemorySize, RING_BYTES);

    ssim_zero_k<<<1, 1>>>();
    ssim_main_k<<<NBLK, TPB, RING_BYTES>>>(img1, img2, window);
    ssim_final_k<<<1, 1>>>((float*)d_out);
}

// round 2
// speedup vs baseline: 1.1181x; 1.1181x over previous
#include <cuda_runtime.h>

// SSIM loss: B=64, C=1, H=W=512, 11x11 uniform box window (1/121), SAME zero padding.
// out = 1 - mean( ret * cs ).
//
// Separable box filter, 4 sums per pixel: E1=box(x), E2=box(y), E3=box(xy), E4=box(x^2+y^2).
// Thread-private 4-column group of a 64-row strip:
//   - horizontal 11-tap sums as depth-4 trees + parallel slide deltas
//   - vertical running sums via per-thread float4 ring in shared (conflict-free)
//   - software-pipelined row loads (ping-pong register buffers) to hide L2 latency
// Single kernel: per-block partials + last-block reduction (no helper launches).

#define WID    512
#define HEI    512
#define RH     64
#define TPB    128
#define NBLK   512
#define RING_BYTES (11 * 4 * TPB * (int)sizeof(float4))  // 90112 B

__device__ float    g_part[NBLK];
__device__ unsigned g_cnt;   // static-init 0; last block resets to 0

__device__ __forceinline__ float ssim_val(float e1, float e2, float e3, float e4,
                                          float w, float w2) {
    const float C1 = 1.6384f;
    const float C2 = 14.7456f;
    float P  = e1 * e2;
    float Q  = fmaf(e1, e1, e2 * e2);
    float A  = w2 * P;
    float B  = w2 * Q;
    float n1 = fmaf(2.f, A, C1);
    float d1 = B + C1;
    float n2 = fmaf(2.f * w, e3, fmaf(-2.f, A, C2));
    float d2 = fmaf(w, e4, C2 - B);
    return __fdividef(n1 * n2, d1 * d2);
}

__global__ void __launch_bounds__(TPB, 2)
ssim_k(const float* __restrict__ img1, const float* __restrict__ img2,
       const float* __restrict__ window, float* __restrict__ out)
{
    extern __shared__ float4 ring[];   // [(slot*4+q)*TPB + h]
    const int h     = threadIdx.x;
    const int b     = blockIdx.x >> 3;
    const int strip = blockIdx.x & 7;
    const int r0    = strip * RH;
    const int c0    = h << 2;

    const float w  = __ldg(window);    // 1/121
    const float w2 = w * w;

    const float* p1 = img1 + (size_t)b * (HEI * WID) + (c0 - 8);
    const float* p2 = img2 + (size_t)b * (HEI * WID) + (c0 - 8);

    // per-float4 span validity (span = 5 float4 covering cols [c0-8, c0+12))
    const bool kp0 = (h >= 2);
    const bool kp1 = (h >= 1);
    const bool kp3 = (h <= 126);
    const bool kp4 = (h <= 125);

    const float4 z4 = make_float4(0.f, 0.f, 0.f, 0.f);
    #pragma unroll
    for (int s = 0; s < 44; s++) ring[s * TPB + h] = z4;

    float4 vs0 = z4, vs1 = z4, vs2 = z4, vs3 = z4;
    float acc = 0.f;
    int slot = 0;

    float xA[20], yA[20], xB[20], yB[20];

    auto load_row = [&](float (&x)[20], float (&y)[20], int r) {
        bool v = ((unsigned)r < (unsigned)HEI);
        const float4* q1 = (const float4*)(p1 + r * WID);
        const float4* q2 = (const float4*)(p2 + r * WID);
        float4 t;
        t = (v && kp0) ? __ldg(q1 + 0) : z4; x[0]=t.x; x[1]=t.y; x[2]=t.z; x[3]=t.w;
        t = (v && kp1) ? __ldg(q1 + 1) : z4; x[4]=t.x; x[5]=t.y; x[6]=t.z; x[7]=t.w;
        t =  v         ? __ldg(q1 + 2) : z4; x[8]=t.x; x[9]=t.y; x[10]=t.z; x[11]=t.w;
        t = (v && kp3) ? __ldg(q1 + 3) : z4; x[12]=t.x; x[13]=t.y; x[14]=t.z; x[15]=t.w;
        t = (v && kp4) ? __ldg(q1 + 4) : z4; x[16]=t.x; x[17]=t.y; x[18]=t.z; x[19]=t.w;
        t = (v && kp0) ? __ldg(q2 + 0) : z4; y[0]=t.x; y[1]=t.y; y[2]=t.z; y[3]=t.w;
        t = (v && kp1) ? __ldg(q2 + 1) : z4; y[4]=t.x; y[5]=t.y; y[6]=t.z; y[7]=t.w;
        t =  v         ? __ldg(q2 + 2) : z4; y[8]=t.x; y[9]=t.y; y[10]=t.z; y[11]=t.w;
        t = (v && kp3) ? __ldg(q2 + 3) : z4; y[12]=t.x; y[13]=t.y; y[14]=t.z; y[15]=t.w;
        t = (v && kp4) ? __ldg(q2 + 4) : z4; y[16]=t.x; y[17]=t.y; y[18]=t.z; y[19]=t.w;
    };

    auto do_row = [&](const float (&x)[20], const float (&y)[20], bool emit) {
        // ---- E1 (sum x), tree + parallel slide deltas ----
        float4 h1;
        {
            float d1a = x[14]-x[3], d1b = x[15]-x[4], d1c = x[16]-x[5];
            float s01 = x[3]+x[4], s23 = x[5]+x[6], s45 = x[7]+x[8];
            float s67 = x[9]+x[10], s89 = x[11]+x[12];
            h1.x = ((s01+s23)+(s45+s67)) + (s89+x[13]);
            h1.y = h1.x + d1a; h1.z = h1.y + d1b; h1.w = h1.z + d1c;
        }
        // ---- E2 (sum y) ----
        float4 h2;
        {
            float d1a = y[14]-y[3], d1b = y[15]-y[4], d1c = y[16]-y[5];
            float s01 = y[3]+y[4], s23 = y[5]+y[6], s45 = y[7]+y[8];
            float s67 = y[9]+y[10], s89 = y[11]+y[12];
            h2.x = ((s01+s23)+(s45+s67)) + (s89+y[13]);
            h2.y = h2.x + d1a; h2.z = h2.y + d1b; h2.w = h2.z + d1c;
        }
        // ---- E3 (sum x*y) ----
        float4 h3;
        {
            float p3 = x[3]*y[3], p4 = x[4]*y[4], p5 = x[5]*y[5];
            float cB = fmaf(x[9],y[9], fmaf(x[8],y[8], fmaf(x[7],y[7], x[6]*y[6])));
            float cC = fmaf(x[13],y[13], fmaf(x[12],y[12], fmaf(x[11],y[11], x[10]*y[10])));
            h3.x = ((p3+p4)+p5) + (cB+cC);
            float u1 = fmaf(x[14],y[14], -p3);
            float u2 = fmaf(x[15],y[15], -p4);
            float u3 = fmaf(x[16],y[16], -p5);
            h3.y = h3.x + u1; h3.z = h3.y + u2; h3.w = h3.z + u3;
        }
        // ---- E4 (sum x^2+y^2) ----
        float4 h4;
        {
            float q3 = fmaf(y[3],y[3], x[3]*x[3]);
            float q4 = fmaf(y[4],y[4], x[4]*x[4]);
            float q5 = fmaf(y[5],y[5], x[5]*x[5]);
            float cB = x[6]*x[6];
            cB = fmaf(y[6],y[6],cB); cB = fmaf(x[7],x[7],cB); cB = fmaf(y[7],y[7],cB);
            cB = fmaf(x[8],x[8],cB); cB = fmaf(y[8],y[8],cB);
            cB = fmaf(x[9],x[9],cB); cB = fmaf(y[9],y[9],cB);
            float cC = x[10]*x[10];
            cC = fmaf(y[10],y[10],cC); cC = fmaf(x[11],x[11],cC); cC = fmaf(y[11],y[11],cC);
            cC = fmaf(x[12],x[12],cC); cC = fmaf(y[12],y[12],cC);
            cC = fmaf(x[13],x[13],cC); cC = fmaf(y[13],y[13],cC);
            h4.x = ((q3+q4)+q5) + (cB+cC);
            float v1 = fmaf(x[14],x[14], -q3); v1 = fmaf(y[14],y[14], v1);
            float v2 = fmaf(x[15],x[15], -q4); v2 = fmaf(y[15],y[15], v2);
            float v3 = fmaf(x[16],x[16], -q5); v3 = fmaf(y[16],y[16], v3);
            h4.y = h4.x + v1; h4.z = h4.y + v2; h4.w = h4.z + v3;
        }

        // ---- vertical ring update ----
        float4* rp = ring + slot * (4 * TPB) + h;
        float4 o0 = rp[0];
        float4 o1 = rp[TPB];
        float4 o2 = rp[2*TPB];
        float4 o3 = rp[3*TPB];
        rp[0] = h1; rp[TPB] = h2; rp[2*TPB] = h3; rp[3*TPB] = h4;
        vs0.x += h1.x-o0.x; vs0.y += h1.y-o0.y; vs0.z += h1.z-o0.z; vs0.w += h1.w-o0.w;
        vs1.x += h2.x-o1.x; vs1.y += h2.y-o1.y; vs1.z += h2.z-o1.z; vs1.w += h2.w-o1.w;
        vs2.x += h3.x-o2.x; vs2.y += h3.y-o2.y; vs2.z += h3.z-o2.z; vs2.w += h3.w-o2.w;
        vs3.x += h4.x-o3.x; vs3.y += h4.y-o3.y; vs3.z += h4.z-o3.z; vs3.w += h4.w-o3.w;
        slot = (slot == 10) ? 0 : slot + 1;

        if (emit) {
            float v0 = ssim_val(vs0.x, vs1.x, vs2.x, vs3.x, w, w2);
            float v1 = ssim_val(vs0.y, vs1.y, vs2.y, vs3.y, w, w2);
            float v2 = ssim_val(vs0.z, vs1.z, vs2.z, vs3.z, w, w2);
            float v3 = ssim_val(vs0.w, vs1.w, vs2.w, vs3.w, w, w2);
            acc += (v0 + v1) + (v2 + v3);
        }
    };

    // ---- software-pipelined row loop ----
    int r = r0 - 5;
    load_row(xA, yA, r);
    // warmup: 10 rows, no emit
    for (int i = 0; i < 10; i += 2) {
        load_row(xB, yB, r + 1); do_row(xA, yA, false);
        load_row(xA, yA, r + 2); do_row(xB, yB, false);
        r += 2;
    }
    // main: 64 rows, emit
    #pragma unroll 2
    for (int i = 0; i < RH; i += 2) {
        load_row(xB, yB, r + 1); do_row(xA, yA, true);
        load_row(xA, yA, r + 2); do_row(xB, yB, true);
        r += 2;
    }

    // ---- block reduction ----
    #pragma unroll
    for (int o = 16; o > 0; o >>= 1)
        acc += __shfl_xor_sync(0xffffffffu, acc, o);
    __shared__ float wsum[4];
    __shared__ int lastflag;
    int wid = h >> 5, lane = h & 31;
    if (lane == 0) wsum[wid] = acc;
    __syncthreads();
    if (h == 0) {
        float bs = (wsum[0] + wsum[1]) + (wsum[2] + wsum[3]);
        g_part[blockIdx.x] = bs;
        __threadfence();
        unsigned t = atomicAdd(&g_cnt, 1u);
        lastflag = (t == NBLK - 1) ? 1 : 0;
    }
    __syncthreads();

    if (lastflag) {
        volatile float* vp = g_part;
        double d = (double)vp[h] + (double)vp[h + 128]
                 + (double)vp[h + 256] + (double)vp[h + 384];
        #pragma unroll
        for (int o = 16; o > 0; o >>= 1)
            d += __shfl_xor_sync(0xffffffffu, d, o);
        __shared__ double dsum[4];
        if (lane == 0) dsum[wid] = d;
        __syncthreads();
        if (h == 0) {
            double tot = (dsum[0] + dsum[1]) + (dsum[2] + dsum[3]);
            out[0] = (float)(1.0 - tot * (1.0 / 16777216.0));
            g_cnt = 0;  // reset for next graph replay
        }
    }
}

extern "C" void kernel_launch(void* const* d_in, const int* in_sizes, int n_in,
                              void* d_out, int out_size)
{
    const float* img1   = (const float*)d_in[0];
    const float* img2   = (const float*)d_in[1];
    const float* window = (const float*)d_in[2];
    (void)in_sizes; (void)n_in; (void)out_size;

    cudaFuncSetAttribute(ssim_k,
                         cudaFuncAttributeMaxDynamicSharedMemorySize, RING_BYTES);
    ssim_k<<<NBLK, TPB, RING_BYTES>>>(img1, img2, window, (float*)d_out);
}

// round 3
// speedup vs baseline: 1.7921x; 1.6028x over previous
#include <cuda_runtime.h>
#include <cuda_fp16.h>

// SSIM loss: B=64, C=1, H=W=512, 11x11 uniform box window (1/121), SAME zero padding.
// out = 1 - mean( ret * cs ).
//
// Separable box filter, 4 sums per pixel: E1=box(x), E2=box(y), E3=box(xy), E4=box(x^2+y^2).
// Thread-private 4-column group of a 64-row strip:
//   - horizontal 11-tap sums as depth-4 trees + parallel slide deltas
//   - vertical running sums via per-thread ring in shared, stored as fp16x4 (8B/quantity)
//     -> ring is 45KB/block -> 4 blocks/SM (occupancy doubled vs fp32 ring)
//   - telescoping is exact: vertical sums add/subtract the fp16-ROUNDED values
//   - software-pipelined row loads (ping-pong register buffers)
// Single kernel: per-block partials + last-block reduction.

#define WID    512
#define HEI    512
#define RH     64
#define TPB    128
#define NBLK   512
#define RING_BYTES (11 * 4 * TPB * (int)sizeof(uint2))  // 45056 B

__device__ float    g_part[NBLK];
__device__ unsigned g_cnt;   // zero-init; last block resets to 0 each replay

__device__ __forceinline__ uint2 pack4(float4 v) {
    __half2 lo = __floats2half2_rn(v.x, v.y);
    __half2 hi = __floats2half2_rn(v.z, v.w);
    uint2 u;
    u.x = *reinterpret_cast<unsigned*>(&lo);
    u.y = *reinterpret_cast<unsigned*>(&hi);
    return u;
}

__device__ __forceinline__ float4 unpack4(uint2 u) {
    __half2 lo = *reinterpret_cast<__half2*>(&u.x);
    __half2 hi = *reinterpret_cast<__half2*>(&u.y);
    float2 a = __half22float2(lo);
    float2 b = __half22float2(hi);
    return make_float4(a.x, a.y, b.x, b.y);
}

__device__ __forceinline__ float ssim_val(float e1, float e2, float e3, float e4,
                                          float w, float w2) {
    const float C1 = 1.6384f;
    const float C2 = 14.7456f;
    float P  = e1 * e2;
    float Q  = fmaf(e1, e1, e2 * e2);
    float A  = w2 * P;
    float B  = w2 * Q;
    float n1 = fmaf(2.f, A, C1);
    float d1 = B + C1;
    float n2 = fmaf(2.f * w, e3, fmaf(-2.f, A, C2));
    float d2 = fmaf(w, e4, C2 - B);
    return __fdividef(n1 * n2, d1 * d2);
}

__global__ void __launch_bounds__(TPB, 4)
ssim_k(const float* __restrict__ img1, const float* __restrict__ img2,
       const float* __restrict__ window, float* __restrict__ out)
{
    extern __shared__ uint2 ring[];   // [(slot*4+q)*TPB + h], fp16x4 per entry
    const int h     = threadIdx.x;
    const int b     = blockIdx.x >> 3;
    const int strip = blockIdx.x & 7;
    const int r0    = strip * RH;
    const int c0    = h << 2;

    const float w  = __ldg(window);    // 1/121
    const float w2 = w * w;

    const float* p1 = img1 + (size_t)b * (HEI * WID) + (c0 - 8);
    const float* p2 = img2 + (size_t)b * (HEI * WID) + (c0 - 8);

    const bool kp0 = (h >= 2);
    const bool kp1 = (h >= 1);
    const bool kp3 = (h <= 126);
    const bool kp4 = (h <= 125);

    const float4 z4 = make_float4(0.f, 0.f, 0.f, 0.f);
    const uint2  zu = make_uint2(0u, 0u);
    #pragma unroll
    for (int s = 0; s < 44; s++) ring[s * TPB + h] = zu;

    float4 vs0 = z4, vs1 = z4, vs2 = z4, vs3 = z4;
    float acc = 0.f;
    int slot = 0;

    float xA[20], yA[20], xB[20], yB[20];

    auto load_row = [&](float (&x)[20], float (&y)[20], int r) {
        bool v = ((unsigned)r < (unsigned)HEI);
        const float4* q1 = (const float4*)(p1 + r * WID);
        const float4* q2 = (const float4*)(p2 + r * WID);
        float4 t;
        t = (v && kp0) ? __ldg(q1 + 0) : z4; x[0]=t.x; x[1]=t.y; x[2]=t.z; x[3]=t.w;
        t = (v && kp1) ? __ldg(q1 + 1) : z4; x[4]=t.x; x[5]=t.y; x[6]=t.z; x[7]=t.w;
        t =  v         ? __ldg(q1 + 2) : z4; x[8]=t.x; x[9]=t.y; x[10]=t.z; x[11]=t.w;
        t = (v && kp3) ? __ldg(q1 + 3) : z4; x[12]=t.x; x[13]=t.y; x[14]=t.z; x[15]=t.w;
        t = (v && kp4) ? __ldg(q1 + 4) : z4; x[16]=t.x; x[17]=t.y; x[18]=t.z; x[19]=t.w;
        t = (v && kp0) ? __ldg(q2 + 0) : z4; y[0]=t.x; y[1]=t.y; y[2]=t.z; y[3]=t.w;
        t = (v && kp1) ? __ldg(q2 + 1) : z4; y[4]=t.x; y[5]=t.y; y[6]=t.z; y[7]=t.w;
        t =  v         ? __ldg(q2 + 2) : z4; y[8]=t.x; y[9]=t.y; y[10]=t.z; y[11]=t.w;
        t = (v && kp3) ? __ldg(q2 + 3) : z4; y[12]=t.x; y[13]=t.y; y[14]=t.z; y[15]=t.w;
        t = (v && kp4) ? __ldg(q2 + 4) : z4; y[16]=t.x; y[17]=t.y; y[18]=t.z; y[19]=t.w;
    };

    auto do_row = [&](const float (&x)[20], const float (&y)[20], bool emit) {
        // ---- horizontal 11-tap sums (trees + parallel slide deltas) ----
        float4 h1;
        {
            float d1a = x[14]-x[3], d1b = x[15]-x[4], d1c = x[16]-x[5];
            float s01 = x[3]+x[4], s23 = x[5]+x[6], s45 = x[7]+x[8];
            float s67 = x[9]+x[10], s89 = x[11]+x[12];
            h1.x = ((s01+s23)+(s45+s67)) + (s89+x[13]);
            h1.y = h1.x + d1a; h1.z = h1.y + d1b; h1.w = h1.z + d1c;
        }
        float4 h2;
        {
            float d1a = y[14]-y[3], d1b = y[15]-y[4], d1c = y[16]-y[5];
            float s01 = y[3]+y[4], s23 = y[5]+y[6], s45 = y[7]+y[8];
            float s67 = y[9]+y[10], s89 = y[11]+y[12];
            h2.x = ((s01+s23)+(s45+s67)) + (s89+y[13]);
            h2.y = h2.x + d1a; h2.z = h2.y + d1b; h2.w = h2.z + d1c;
        }
        float4 h3;
        {
            float p3 = x[3]*y[3], p4 = x[4]*y[4], p5 = x[5]*y[5];
            float cB = fmaf(x[9],y[9], fmaf(x[8],y[8], fmaf(x[7],y[7], x[6]*y[6])));
            float cC = fmaf(x[13],y[13], fmaf(x[12],y[12], fmaf(x[11],y[11], x[10]*y[10])));
            h3.x = ((p3+p4)+p5) + (cB+cC);
            float u1 = fmaf(x[14],y[14], -p3);
            float u2 = fmaf(x[15],y[15], -p4);
            float u3 = fmaf(x[16],y[16], -p5);
            h3.y = h3.x + u1; h3.z = h3.y + u2; h3.w = h3.z + u3;
        }
        float4 h4;
        {
            float q3 = fmaf(y[3],y[3], x[3]*x[3]);
            float q4 = fmaf(y[4],y[4], x[4]*x[4]);
            float q5 = fmaf(y[5],y[5], x[5]*x[5]);
            float cB = x[6]*x[6];
            cB = fmaf(y[6],y[6],cB); cB = fmaf(x[7],x[7],cB); cB = fmaf(y[7],y[7],cB);
            cB = fmaf(x[8],x[8],cB); cB = fmaf(y[8],y[8],cB);
            cB = fmaf(x[9],x[9],cB); cB = fmaf(y[9],y[9],cB);
            float cC = x[10]*x[10];
            cC = fmaf(y[10],y[10],cC); cC = fmaf(x[11],x[11],cC); cC = fmaf(y[11],y[11],cC);
            cC = fmaf(x[12],x[12],cC); cC = fmaf(y[12],y[12],cC);
            cC = fmaf(x[13],x[13],cC); cC = fmaf(y[13],y[13],cC);
            h4.x = ((q3+q4)+q5) + (cB+cC);
            float v1 = fmaf(x[14],x[14], -q3); v1 = fmaf(y[14],y[14], v1);
            float v2 = fmaf(x[15],x[15], -q4); v2 = fmaf(y[15],y[15], v2);
            float v3 = fmaf(x[16],x[16], -q5); v3 = fmaf(y[16],y[16], v3);
            h4.y = h4.x + v1; h4.z = h4.y + v2; h4.w = h4.z + v3;
        }

        // ---- vertical ring update (fp16 ring; exact telescoping on rounded values) ----
        uint2* rp = ring + slot * (4 * TPB) + h;
        uint2 po0 = rp[0];
        uint2 po1 = rp[TPB];
        uint2 po2 = rp[2*TPB];
        uint2 po3 = rp[3*TPB];
        uint2 pn0 = pack4(h1), pn1 = pack4(h2), pn2 = pack4(h3), pn3 = pack4(h4);
        rp[0] = pn0; rp[TPB] = pn1; rp[2*TPB] = pn2; rp[3*TPB] = pn3;
        float4 n0 = unpack4(pn0), o0 = unpack4(po0);
        float4 n1 = unpack4(pn1), o1 = unpack4(po1);
        float4 n2 = unpack4(pn2), o2 = unpack4(po2);
        float4 n3 = unpack4(pn3), o3 = unpack4(po3);
        vs0.x += n0.x-o0.x; vs0.y += n0.y-o0.y; vs0.z += n0.z-o0.z; vs0.w += n0.w-o0.w;
        vs1.x += n1.x-o1.x; vs1.y += n1.y-o1.y; vs1.z += n1.z-o1.z; vs1.w += n1.w-o1.w;
        vs2.x += n2.x-o2.x; vs2.y += n2.y-o2.y; vs2.z += n2.z-o2.z; vs2.w += n2.w-o2.w;
        vs3.x += n3.x-o3.x; vs3.y += n3.y-o3.y; vs3.z += n3.z-o3.z; vs3.w += n3.w-o3.w;
        slot = (slot == 10) ? 0 : slot + 1;

        if (emit) {
            float v0 = ssim_val(vs0.x, vs1.x, vs2.x, vs3.x, w, w2);
            float v1 = ssim_val(vs0.y, vs1.y, vs2.y, vs3.y, w, w2);
            float v2 = ssim_val(vs0.z, vs1.z, vs2.z, vs3.z, w, w2);
            float v3 = ssim_val(vs0.w, vs1.w, vs2.w, vs3.w, w, w2);
            acc += (v0 + v1) + (v2 + v3);
        }
    };

    // ---- software-pipelined row loop ----
    int r = r0 - 5;
    load_row(xA, yA, r);
    for (int i = 0; i < 10; i += 2) {          // warmup, no emit
        load_row(xB, yB, r + 1); do_row(xA, yA, false);
        load_row(xA, yA, r + 2); do_row(xB, yB, false);
        r += 2;
    }
    #pragma unroll 2
    for (int i = 0; i < RH; i += 2) {          // main, emit
        load_row(xB, yB, r + 1); do_row(xA, yA, true);
        load_row(xA, yA, r + 2); do_row(xB, yB, true);
        r += 2;
    }

    // ---- block reduction ----
    #pragma unroll
    for (int o = 16; o > 0; o >>= 1)
        acc += __shfl_xor_sync(0xffffffffu, acc, o);
    __shared__ float wsum[4];
    __shared__ int lastflag;
    int wid = h >> 5, lane = h & 31;
    if (lane == 0) wsum[wid] = acc;
    __syncthreads();
    if (h == 0) {
        float bs = (wsum[0] + wsum[1]) + (wsum[2] + wsum[3]);
        g_part[blockIdx.x] = bs;
        __threadfence();
        unsigned t = atomicAdd(&g_cnt, 1u);
        lastflag = (t == NBLK - 1) ? 1 : 0;
    }
    __syncthreads();

    if (lastflag) {
        volatile float* vp = g_part;
        double d = (double)vp[h] + (double)vp[h + 128]
                 + (double)vp[h + 256] + (double)vp[h + 384];
        #pragma unroll
        for (int o = 16; o > 0; o >>= 1)
            d += __shfl_xor_sync(0xffffffffu, d, o);
        __shared__ double dsum[4];
        if (lane == 0) dsum[wid] = d;
        __syncthreads();
        if (h == 0) {
            double tot = (dsum[0] + dsum[1]) + (dsum[2] + dsum[3]);
            out[0] = (float)(1.0 - tot * (1.0 / 16777216.0));
            g_cnt = 0;
        }
    }
}

extern "C" void kernel_launch(void* const* d_in, const int* in_sizes, int n_in,
                              void* d_out, int out_size)
{
    const float* img1   = (const float*)d_in[0];
    const float* img2   = (const float*)d_in[1];
    const float* window = (const float*)d_in[2];
    (void)in_sizes; (void)n_in; (void)out_size;

    cudaFuncSetAttribute(ssim_k,
                         cudaFuncAttributeMaxDynamicSharedMemorySize, RING_BYTES);
    ssim_k<<<NBLK, TPB, RING_BYTES>>>(img1, img2, window, (float*)d_out);
}